// round 16
// baseline (speedup 1.0000x reference)
#include <cuda_runtime.h>
#include <math.h>

#define EPSV 1e-5f
#define L2E 1.4426950408889634f

// ---------------- scratch ----------------
__device__ float g_t1a[32*3*252*252];
__device__ float g_t2a[32*3*252*252];
__device__ float g_t1b[32*3*252*252];
__device__ float g_t2b[32*3*252*252];
__device__ float g_bufA[32*3*1024];
__device__ float g_bufB[32*3*1024];
__device__ float g_stats[12*96*2];
__device__ float g_AB12[12*96*2];
__device__ int   g_ticket[12];
__device__ float g_noiseB[3*64*64];
__device__ float4 g_q4[32*1024];
__device__ float4 g_k4[32*1024];
__device__ float4 g_v4[32*1024];
__device__ float4 g_w4[32*1024];

// ---------------- tiny helpers ----------------
__device__ __forceinline__ float ex2(float x) {
    float r; asm("ex2.approx.ftz.f32 %0,%1;" : "=f"(r) : "f"(x)); return r;
}
__device__ __forceinline__ float frcp(float x) {
    float r; asm("rcp.approx.ftz.f32 %0,%1;" : "=f"(r) : "f"(x)); return r;
}
__device__ __forceinline__ float ftanh(float x) {
    float e = ex2(x * 2.885390081777927f);
    return fmaf(-2.f, frcp(e + 1.f), 1.f);
}

// ---------------- stats reduction ----------------
__device__ __forceinline__ void stats_reduce(float s0, float s1, float s2,
                                             float q0, float q1, float q2,
                                             float* stats, int n) {
    #pragma unroll
    for (int off = 16; off; off >>= 1) {
        s0 += __shfl_down_sync(0xffffffffu, s0, off);
        s1 += __shfl_down_sync(0xffffffffu, s1, off);
        s2 += __shfl_down_sync(0xffffffffu, s2, off);
        q0 += __shfl_down_sync(0xffffffffu, q0, off);
        q1 += __shfl_down_sync(0xffffffffu, q1, off);
        q2 += __shfl_down_sync(0xffffffffu, q2, off);
    }
    __shared__ float rb[8][6];
    int warp = threadIdx.x >> 5, lane = threadIdx.x & 31;
    if (lane == 0) {
        rb[warp][0]=s0; rb[warp][1]=s1; rb[warp][2]=s2;
        rb[warp][3]=q0; rb[warp][4]=q1; rb[warp][5]=q2;
    }
    __syncthreads();
    if (threadIdx.x == 0) {
        float a[6] = {0,0,0,0,0,0};
        int nw = blockDim.x >> 5;
        for (int wi = 0; wi < nw; wi++)
            for (int t = 0; t < 6; t++) a[t] += rb[wi][t];
        #pragma unroll
        for (int c = 0; c < 3; c++) {
            atomicAdd(&stats[(n*3+c)*2+0], a[c]);
            atomicAdd(&stats[(n*3+c)*2+1], a[3+c]);
        }
    }
}

// ---------------- last-block finalize ----------------
__device__ __forceinline__ void finalize_if_last(const float* __restrict__ st, float* __restrict__ ab,
        int* ticket, int nblocks,
        const float* ip, const float* lp, const float* bp,
        const float* bnw, const float* bnb, const float* p1p, int N, float cnt) {
    __shared__ int slast;
    if (threadIdx.x == 0) {
        __threadfence();
        int t = atomicAdd(ticket, 1);
        slast = (t == nblocks - 1) ? 1 : 0;
    }
    __syncthreads();
    if (!slast) return;
    __shared__ float s_s[96], s_q[96], s_bs[3], s_bq[3];
    int tid = threadIdx.x;
    if (tid < N*3) {
        s_s[tid] = __ldcg(st + tid*2);
        s_q[tid] = __ldcg(st + tid*2 + 1);
    }
    __syncthreads();
    if (tid < 3) {
        float a = 0.f, b = 0.f;
        for (int n = 0; n < N; n++) { a += s_s[n*3+tid]; b += s_q[n*3+tid]; }
        s_bs[tid] = a; s_bq[tid] = b;
    }
    __syncthreads();
    if (tid < N*3) {
        int c = tid % 3;
        float mI = s_s[tid]/cnt, vI = s_q[tid]/cnt - mI*mI;
        float rI = rsqrtf(vI + EPSV);
        float cb = cnt * (float)N;
        float mB = s_bs[c]/cb, vB = s_bq[c]/cb - mB*mB;
        float rB = rsqrtf(vB + EPSV);
        float alpha = __ldg(ip)+__ldg(ip+1)+__ldg(ip+2)+__ldg(lp)+__ldg(lp+1)+__ldg(lp+2);
        float beta  = __ldg(bp)+__ldg(bp+1)+__ldg(bp+2);
        float bw = __ldg(bnw+c), bb2 = __ldg(bnb+c), P1 = __ldg(p1p);
        ab[tid*2]   = P1*(1.f + alpha*rI + beta*rB*bw);
        ab[tid*2+1] = P1*(beta*(bb2 - mB*rB*bw) - alpha*mI*rI);
    }
}

// ---------------- weight pack ----------------
__device__ __forceinline__ void load_weights(const float* w1, const float* w2, float* sw8) {
    for (int j = threadIdx.x; j < 600; j += blockDim.x) {
        int slot = j & 7, pos = j >> 3;
        float v = 0.f;
        if (slot < 3)      v = __ldg(w1 + slot*75 + pos);
        else if (slot < 6) v = __ldg(w2 + (slot-3)*75 + pos);
        sw8[j] = v;
    }
}

// ---------------- upsample-path conv ----------------
template<int Hin, int Hc, int r, int RPB, int SPREV, int LGIN, bool FUSED>
__global__ void __launch_bounds__(256, 4)
k_conv_up_t(const float* __restrict__ in,
            const float* __restrict__ pt1, const float* __restrict__ pt2,
            const float* __restrict__ pab, const float* pp2,
            float* __restrict__ ot1, float* __restrict__ ot2,
            const float* __restrict__ w1, const float* __restrict__ b1,
            const float* __restrict__ w2, const float* __restrict__ b2,
            float* stats, float* ab, int* ticket, int nblocks,
            const float* ip, const float* lp, const float* bp,
            const float* bnw, const float* bnb, const float* p1p) {
    constexpr int SR = RPB + 4;
    __shared__ float sw8[600];
    extern __shared__ float dsin[];           // [3][SR][Hin]
    load_weights(w1, w2, sw8);
    int n = blockIdx.y;
    int h0 = blockIdx.x * RPB;
    if (FUSED) {
        float P2 = __ldg(pp2);
        for (int j = threadIdx.x; j < 3*SR*Hin; j += 256) {
            int ci = j / (SR*Hin), rem = j - ci*(SR*Hin);
            int row = rem / Hin, col = rem - row*Hin;
            int gr = h0 + row; gr = (gr < Hin) ? gr : Hin-1;
            int nc3 = n*3 + ci;
            float A = __ldg(pab + nc3*2), B = __ldg(pab + nc3*2 + 1);
            int sh2 = (gr*SPREV) >> LGIN, sw2 = (col*SPREV) >> LGIN;
            long sidx = ((long)nc3*SPREV + sh2)*SPREV + sw2;
            dsin[(ci*SR + row)*Hin + col] =
                fmaf(__ldg(pt1 + sidx), A, B) + P2*__ldg(pt2 + sidx);
        }
    } else {
        constexpr int W4 = Hin / 4;
        const float4* src = (const float4*)(in + (long)n*3*Hin*Hin);
        for (int j = threadIdx.x; j < 3*SR*W4; j += 256) {
            int ci = j / (SR*W4), rem = j - ci*(SR*W4);
            int row = rem / W4, col = rem - row*W4;
            int gr = h0 + row; gr = (gr < Hin) ? gr : Hin-1;
            ((float4*)dsin)[(ci*SR + row)*W4 + col] = __ldg(src + (ci*Hin + gr)*W4 + col);
        }
    }
    __syncthreads();
    int warp = threadIdx.x >> 5, lane = threadIdx.x & 31;
    int rloc = warp % RPB;
    int sgrp = warp / RPB;
    constexpr int NSG = 8 / RPB;
    int sh = h0 + rloc;
    constexpr int STRIPS = Hc / 4;
    float a0=0,a1=0,a2=0,q0=0,q1=0,q2=0;
    if (sh < Hc) {
        float wrow = (float)((((sh+1)*r + Hc - 1)/Hc) - ((sh*r + Hc - 1)/Hc));
        #pragma unroll 1
        for (int strip = lane + 32*sgrp; strip < STRIPS; strip += 32*NSG) {
            int sw0 = strip * 4;
            float acc[6][4];
            #pragma unroll
            for (int f = 0; f < 6; f++) {
                float bb = (f < 3) ? __ldg(b1+f) : __ldg(b2+f-3);
                #pragma unroll
                for (int p = 0; p < 4; p++) acc[f][p] = bb;
            }
            #pragma unroll
            for (int ci = 0; ci < 3; ci++) {
                #pragma unroll
                for (int kh = 0; kh < 5; kh++) {
                    const float* srow = dsin + ((ci*SR + rloc + kh)*Hin + sw0);
                    float4 xa = *(const float4*)(srow);
                    float4 xb = *(const float4*)(srow + 4);
                    float xv[8] = {xa.x, xa.y, xa.z, xa.w, xb.x, xb.y, xb.z, xb.w};
                    const float* wr = sw8 + (ci*25 + kh*5)*8;
                    #pragma unroll
                    for (int kw = 0; kw < 5; kw++) {
                        float4 wa = *(const float4*)(wr + kw*8);
                        float2 wb = *(const float2*)(wr + kw*8 + 4);
                        #pragma unroll
                        for (int p = 0; p < 4; p++) {
                            float xx = xv[p+kw];
                            acc[0][p] = fmaf(wa.x, xx, acc[0][p]);
                            acc[1][p] = fmaf(wa.y, xx, acc[1][p]);
                            acc[2][p] = fmaf(wa.z, xx, acc[2][p]);
                            acc[3][p] = fmaf(wa.w, xx, acc[3][p]);
                            acc[4][p] = fmaf(wb.x, xx, acc[4][p]);
                            acc[5][p] = fmaf(wb.y, xx, acc[5][p]);
                        }
                    }
                }
            }
            constexpr int chs = Hc*Hc;
            long base = ((long)(n*3)*Hc + sh)*Hc + sw0;
            #pragma unroll
            for (int p = 0; p < 4; p++) {
                int swp = sw0 + p;
                float wcol = (float)((((swp+1)*r + Hc - 1)/Hc) - ((swp*r + Hc - 1)/Hc));
                float wgt = wrow * wcol;
                float y0 = acc[0][p], y1 = acc[1][p], y2 = acc[2][p];
                ot1[base + p]         = y0;
                ot1[base + chs + p]   = y1;
                ot1[base + 2*chs + p] = y2;
                ot2[base + p]         = acc[3][p];
                ot2[base + chs + p]   = acc[4][p];
                ot2[base + 2*chs + p] = acc[5][p];
                a0 += wgt*y0; q0 += wgt*y0*y0;
                a1 += wgt*y1; q1 += wgt*y1*y1;
                a2 += wgt*y2; q2 += wgt*y2*y2;
            }
        }
    }
    stats_reduce(a0, a1, a2, q0, q1, q2, stats, n);
    finalize_if_last(stats, ab, ticket, nblocks, ip, lp, bp, bnw, bnb, p1p, 32, (float)(r*r));
}

// ---------------- downsample-path conv ----------------
template<int Hin, int Hc, int r, int LGR, int TW, int PC, int RPB, int SPREV, int LGIN, bool FUSED, bool NOISE>
__global__ void __launch_bounds__(256, 4)
k_conv_dir_t(const float* __restrict__ in,
             const float* __restrict__ pt1, const float* __restrict__ pt2,
             const float* __restrict__ pab, const float* pp2,
             const float* __restrict__ pnoise,
             float* __restrict__ ot1, float* __restrict__ ot2,
             const float* __restrict__ w1, const float* __restrict__ b1,
             const float* __restrict__ w2, const float* __restrict__ b2,
             float* stats, float* ab, int* ticket, int nblocks,
             const float* ip, const float* lp, const float* bp,
             const float* bnw, const float* bnb, const float* p1p) {
    constexpr int NROWS = ((RPB-1)*Hc)/r + 6;
    constexpr int XT = r / TW;
    __shared__ float sw8[600];
    extern __shared__ float dsin[];           // [3][NROWS][PC]
    load_weights(w1, w2, sw8);
    int n = blockIdx.y;
    int tile = blockIdx.x;
    int tyt = tile / XT, txt = tile - tyt*XT;
    int h0 = tyt * RPB;
    int w0 = txt * TW;
    int s0 = (h0*Hc) >> LGR;
    int sw0a = ((w0*Hc) >> LGR) & ~3;
    if (FUSED) {
        float P2 = __ldg(pp2);
        for (int j = threadIdx.x; j < 3*NROWS*PC; j += 256) {
            int ci = j / (NROWS*PC), rem = j - ci*(NROWS*PC);
            int row = rem / PC, col = rem - row*PC;
            int gr = s0 + row; gr = (gr < Hin) ? gr : Hin-1;
            int gc = sw0a + col; gc = (gc < Hin) ? gc : Hin-1;
            int nc3 = n*3 + ci;
            float A = __ldg(pab + nc3*2), B = __ldg(pab + nc3*2 + 1);
            int sh2 = (gr*SPREV) >> LGIN, sw2 = (gc*SPREV) >> LGIN;
            long sidx = ((long)nc3*SPREV + sh2)*SPREV + sw2;
            float v = fmaf(__ldg(pt1 + sidx), A, B) + P2*__ldg(pt2 + sidx);
            if (NOISE) v += __ldg(pnoise + (ci*Hin + gr)*Hin + gc);
            dsin[(ci*NROWS + row)*PC + col] = v;
        }
    } else {
        constexpr int W4 = Hin / 4;
        constexpr int PC4 = PC / 4;
        const float4* src = (const float4*)(in + (long)n*3*Hin*Hin);
        for (int j = threadIdx.x; j < 3*NROWS*PC4; j += 256) {
            int ci = j / (NROWS*PC4), rem = j - ci*(NROWS*PC4);
            int row = rem / PC4, col4 = rem - row*PC4;
            int gr = s0 + row; gr = (gr < Hin) ? gr : Hin-1;
            int gc4 = (sw0a >> 2) + col4; gc4 = (gc4 < W4) ? gc4 : W4-1;
            *(float4*)(dsin + (ci*NROWS + row)*PC + col4*4) = __ldg(src + (ci*Hin + gr)*W4 + gc4);
        }
    }
    __syncthreads();
    int warp = threadIdx.x >> 5, lane = threadIdx.x & 31;
    int rloc = warp % RPB;
    int wgrp = warp / RPB;
    constexpr int NSG = 8 / RPB;
    int h = h0 + rloc;
    int shl = ((h*Hc) >> LGR) - s0;
    float a0=0,a1=0,a2=0,q0=0,q1=0,q2=0;
    #pragma unroll 1
    for (int wi = lane + 32*wgrp; wi < TW; wi += 32*NSG) {
        int w = w0 + wi;
        int swl = ((w*Hc) >> LGR) - sw0a;
        float acc[6];
        #pragma unroll
        for (int f = 0; f < 6; f++)
            acc[f] = (f < 3) ? __ldg(b1+f) : __ldg(b2+f-3);
        #pragma unroll
        for (int ci = 0; ci < 3; ci++) {
            #pragma unroll
            for (int kh = 0; kh < 5; kh++) {
                const float* srow = dsin + ((ci*NROWS + shl + kh)*PC + swl);
                float xv[5];
                #pragma unroll
                for (int j = 0; j < 5; j++) xv[j] = srow[j];
                const float* wr = sw8 + (ci*25 + kh*5)*8;
                #pragma unroll
                for (int kw = 0; kw < 5; kw++) {
                    float4 wa = *(const float4*)(wr + kw*8);
                    float2 wb = *(const float2*)(wr + kw*8 + 4);
                    float xx = xv[kw];
                    acc[0] = fmaf(wa.x, xx, acc[0]);
                    acc[1] = fmaf(wa.y, xx, acc[1]);
                    acc[2] = fmaf(wa.z, xx, acc[2]);
                    acc[3] = fmaf(wa.w, xx, acc[3]);
                    acc[4] = fmaf(wb.x, xx, acc[4]);
                    acc[5] = fmaf(wb.y, xx, acc[5]);
                }
            }
        }
        constexpr int rs = r*r;
        long base = (long)(n*3)*rs + h*r + w;
        ot1[base]        = acc[0];
        ot1[base + rs]   = acc[1];
        ot1[base + 2*rs] = acc[2];
        ot2[base]        = acc[3];
        ot2[base + rs]   = acc[4];
        ot2[base + 2*rs] = acc[5];
        a0 += acc[0]; q0 += acc[0]*acc[0];
        a1 += acc[1]; q1 += acc[1]*acc[1];
        a2 += acc[2]; q2 += acc[2]*acc[2];
    }
    stats_reduce(a0, a1, a2, q0, q1, q2, stats, n);
    finalize_if_last(stats, ab, ticket, nblocks, ip, lp, bp, bnw, bnb, p1p, 32, (float)(r*r));
}

// ---------------- apply (final block only) ----------------
__global__ void k_apply(float* __restrict__ out,
                        const float* __restrict__ t1, const float* __restrict__ t2,
                        const float* __restrict__ ab,
                        const float* p2p, int N, int r, int S, int dotanh) {
    int rq = r >> 2;
    int idx = blockIdx.x*blockDim.x + threadIdx.x;
    if (idx >= N*3*r*rq) return;
    int w0 = (idx % rq)*4; int t = idx / rq; int h = t % r; int nc = t / r;
    float A = __ldg(ab + nc*2), B = __ldg(ab + nc*2 + 1), P2 = __ldg(p2p);
    float v[4];
    if (S == r) {
        long sb = ((long)nc*S + h)*S + w0;
        float4 t1v = *(const float4*)(t1 + sb);
        float4 t2v = *(const float4*)(t2 + sb);
        v[0] = fmaf(t1v.x, A, B) + P2*t2v.x;
        v[1] = fmaf(t1v.y, A, B) + P2*t2v.y;
        v[2] = fmaf(t1v.z, A, B) + P2*t2v.z;
        v[3] = fmaf(t1v.w, A, B) + P2*t2v.w;
    } else {
        int sh = (h*S)/r;
        long rb = ((long)nc*S + sh)*S;
        #pragma unroll
        for (int p = 0; p < 4; p++) {
            int sw = ((w0+p)*S)/r;
            v[p] = fmaf(t1[rb+sw], A, B) + P2*t2[rb+sw];
        }
    }
    if (dotanh) {
        #pragma unroll
        for (int p = 0; p < 4; p++) v[p] = ftanh(v[p]);
    }
    *(float4*)(out + (long)idx*4) = make_float4(v[0], v[1], v[2], v[3]);
}

// ---------------- apply + qkv fused (attention blocks) ----------------
__global__ void k_apply_att(float* __restrict__ out,
                            const float* __restrict__ t1, const float* __restrict__ t2,
                            const float* __restrict__ ab, const float* p2p,
                            const float* qw, const float* qb,
                            const float* kw_, const float* kb,
                            const float* vw, const float* vb,
                            int N, int r, int S) {
    int HW = r*r;
    int idx = blockIdx.x*blockDim.x + threadIdx.x;
    if (idx >= N*HW) return;
    int b = idx / HW, pix = idx - b*HW;
    int h = pix / r, w = pix - h*r;
    int sh = (h*S)/r, sw = (w*S)/r;
    float P2 = __ldg(p2p);
    long sbase = ((long)(b*3)*S + sh)*S + sw;
    int ss2 = S*S;
    float val[3];
    #pragma unroll
    for (int c = 0; c < 3; c++) {
        float A = __ldg(ab + (b*3+c)*2), B = __ldg(ab + (b*3+c)*2 + 1);
        val[c] = fmaf(t1[sbase + c*ss2], A, B) + P2*t2[sbase + c*ss2];
    }
    long ob = (long)b*3*HW + pix;
    out[ob] = val[0]; out[ob+HW] = val[1]; out[ob+2*HW] = val[2];
    float qv[3], kv[3], vv[3];
    #pragma unroll
    for (int o = 0; o < 3; o++) {
        qv[o] = fmaf(__ldg(qw+o*3), val[0], fmaf(__ldg(qw+o*3+1), val[1],
                fmaf(__ldg(qw+o*3+2), val[2], __ldg(qb+o))));
        kv[o] = fmaf(__ldg(kw_+o*3), val[0], fmaf(__ldg(kw_+o*3+1), val[1],
                fmaf(__ldg(kw_+o*3+2), val[2], __ldg(kb+o))));
        vv[o] = fmaf(__ldg(vw+o*3), val[0], fmaf(__ldg(vw+o*3+1), val[1],
                fmaf(__ldg(vw+o*3+2), val[2], __ldg(vb+o))));
    }
    g_q4[b*HW+pix] = make_float4(qv[0], qv[1], qv[2], 0.f);
    g_k4[b*HW+pix] = make_float4(kv[0], kv[1], kv[2], 0.f);
    g_v4[b*HW+pix] = make_float4(vv[0], vv[1], vv[2], 0.f);
}

// ---------------- attention pass 1 (R10-proven, full grid) ----------------
__global__ void k_att1(int HW) {
    __shared__ float4 sq[1024];
    int b = blockIdx.y;
    for (int j = threadIdx.x; j < HW; j += blockDim.x) sq[j] = g_q4[b*HW+j];
    __syncthreads();
    int m = blockIdx.x*blockDim.x + threadIdx.x;
    if (m >= HW) return;
    float4 kk = g_k4[b*HW+m];
    float k0 = kk.x*L2E, k1 = kk.y*L2E, k2 = kk.z*L2E;
    float mx = -1e30f;
    for (int nn = 0; nn < HW; nn++) {
        float4 q = sq[nn];
        float s = fmaf(k0, q.x, fmaf(k1, q.y, k2*q.z));
        mx = fmaxf(mx, s);
    }
    float Z = 0.f;
    for (int nn = 0; nn < HW; nn++) {
        float4 q = sq[nn];
        float s = fmaf(k0, q.x, fmaf(k1, q.y, k2*q.z));
        Z += ex2(s - mx);
    }
    float iz = frcp(Z);
    g_k4[b*HW+m] = make_float4(k0, k1, k2, mx);
    float4 v = g_v4[b*HW+m];
    g_w4[b*HW+m] = make_float4(v.x*iz, v.y*iz, v.z*iz, 0.f);
}

// ---------------- attention pass 2 (R10-proven, full grid) ----------------
__global__ void k_att2(float* __restrict__ out, int HW) {
    __shared__ float4 sk[1024];
    __shared__ float4 sw[1024];
    int b = blockIdx.y;
    for (int j = threadIdx.x; j < HW; j += blockDim.x) {
        sk[j] = g_k4[b*HW+j];
        sw[j] = g_w4[b*HW+j];
    }
    __syncthreads();
    int nn = blockIdx.x*blockDim.x + threadIdx.x;
    if (nn >= HW) return;
    float4 q = g_q4[b*HW+nn];
    float a0 = 0.f, a1 = 0.f, a2 = 0.f;
    for (int m = 0; m < HW; m++) {
        float4 kk = sk[m];
        float s = fmaf(kk.x, q.x, fmaf(kk.y, q.y, kk.z*q.z));
        float e = ex2(s - kk.w);
        float4 w = sw[m];
        a0 = fmaf(w.x, e, a0);
        a1 = fmaf(w.y, e, a1);
        a2 = fmaf(w.z, e, a2);
    }
    long ob = (long)b*3*HW + nn;
    out[ob]        += a0;
    out[ob+HW]     += a1;
    out[ob+2*HW]   += a2;
}

// ---------------- fused noise path (separate launch, R10-proven) ----------------
__device__ void nblock(const float* xin, float* y1, float* y2, float* xout,
                       int Hin, int Hc, int r,
                       const float* w1, const float* b1, const float* w2, const float* b2,
                       const float* ip, const float* lp, const float* bp,
                       const float* bw_, const float* bb_, float P1, float P2) {
    __shared__ float swn[450];
    __shared__ float sacc[6];
    __shared__ float sAB2[6];
    int tid = threadIdx.x, nt = blockDim.x;
    for (int j = tid; j < 450; j += nt) {
        int slot = j % 6, pos = j / 6;
        swn[j] = (slot < 3) ? __ldg(w1 + slot*75 + pos) : __ldg(w2 + (slot-3)*75 + pos);
    }
    if (tid < 6) sacc[tid] = 0.f;
    __syncthreads();
    float ls[6] = {0,0,0,0,0,0};
    int hc2 = Hc*Hc;
    for (int pix = tid; pix < hc2; pix += nt) {
        int sh = pix / Hc, sw = pix - sh*Hc;
        float a[6];
        #pragma unroll
        for (int f = 0; f < 6; f++) a[f] = (f < 3) ? __ldg(b1+f) : __ldg(b2+f-3);
        for (int ci = 0; ci < 3; ci++)
            for (int kh = 0; kh < 5; kh++) {
                const float* row = xin + (ci*Hin + sh + kh)*Hin + sw;
                const float* wr = swn + (ci*25 + kh*5)*6;
                #pragma unroll
                for (int kw = 0; kw < 5; kw++) {
                    float xx = row[kw];
                    #pragma unroll
                    for (int f = 0; f < 6; f++) a[f] = fmaf(wr[kw*6+f], xx, a[f]);
                }
            }
        float wrow = (float)((((sh+1)*r + Hc - 1)/Hc) - ((sh*r + Hc - 1)/Hc));
        float wcol = (float)((((sw+1)*r + Hc - 1)/Hc) - ((sw*r + Hc - 1)/Hc));
        float wgt = wrow * wcol;
        #pragma unroll
        for (int c = 0; c < 3; c++) {
            y1[c*hc2 + pix] = a[c];
            y2[c*hc2 + pix] = a[3+c];
            ls[c]   += wgt * a[c];
            ls[3+c] += wgt * a[c]*a[c];
        }
    }
    #pragma unroll
    for (int j = 0; j < 6; j++) atomicAdd(&sacc[j], ls[j]);
    __syncthreads();
    if (tid < 3) {
        float cnt = (float)(r*r);
        float mI = sacc[tid]/cnt, vI = sacc[3+tid]/cnt - mI*mI;
        float rI = rsqrtf(vI + EPSV);
        float alpha = __ldg(ip)+__ldg(ip+1)+__ldg(ip+2)+__ldg(lp)+__ldg(lp+1)+__ldg(lp+2);
        float beta  = __ldg(bp)+__ldg(bp+1)+__ldg(bp+2);
        float bw = __ldg(bw_+tid), bb2 = __ldg(bb_+tid);
        sAB2[tid]   = P1*(1.f + alpha*rI + beta*rI*bw);
        sAB2[3+tid] = P1*(beta*(bb2 - mI*rI*bw) - alpha*mI*rI);
    }
    __syncthreads();
    int rr = r*r;
    for (int e = tid; e < 3*rr; e += nt) {
        int c = e / rr, pix = e - c*rr;
        int h = pix / r, w = pix - h*r;
        int sh = (h*Hc)/r, sw = (w*Hc)/r;
        int si = c*hc2 + sh*Hc + sw;
        xout[e] = fmaf(y1[si], sAB2[c], sAB2[3+c]) + P2*y2[si];
    }
    __syncthreads();
}

__global__ void k_noise(const float* __restrict__ z,
                        const float* __restrict__ Wl, const float* __restrict__ bl,
                        const float* cw, const float* cb, const float* c2w, const float* c2b,
                        const float* inp, const float* lnp, const float* bnp,
                        const float* bnw, const float* bnb,
                        const float* p1, const float* p2) {
    __shared__ float sl[768];
    __shared__ float y1a[3*144], y2a[3*144];
    __shared__ float x1[3*1024];
    __shared__ float y1b[3*784], y2b[3*784];
    int tid = threadIdx.x;
    for (int j = tid; j < 12*96*2; j += blockDim.x) g_stats[j] = 0.f;
    if (tid < 12) g_ticket[tid] = 0;
    int warp = tid >> 5, lane = tid & 31;
    for (int o = warp; o < 768; o += (int)(blockDim.x >> 5)) {
        const float* w = Wl + o*512;
        float a = 0.f;
        for (int j = lane; j < 512; j += 32) a = fmaf(__ldg(z+j), __ldg(w+j), a);
        #pragma unroll
        for (int off = 16; off; off >>= 1) a += __shfl_down_sync(0xffffffffu, a, off);
        if (lane == 0) sl[o] = a + __ldg(bl + o);
    }
    __syncthreads();
    nblock(sl, y1a, y2a, x1, 16, 12, 32, cw, cb, c2w, c2b,
           inp, lnp, bnp, bnw, bnb, __ldg(p1), __ldg(p2));
    nblock(x1, y1b, y2b, g_noiseB, 32, 28, 64, cw+225, cb+3, c2w+225, c2b+3,
           inp+3, lnp+3, bnp+3, bnw+3, bnb+3, __ldg(p1+1), __ldg(p2+1));
}

// ---------------- host launchers ----------------
struct BP {
    const float *w1, *b1, *w2, *b2;
    float *st, *ab; int *tk;
    const float *ip, *lp, *bpp, *bnw, *bnb, *p1;
};

template<int Hin, int Hc, int r, int RPB, int SPREV, int LGIN, bool FUSED>
static void launch_up(const BP& b, const float* in,
                      const float* pt1, const float* pt2,
                      const float* pab, const float* pp2,
                      float* ot1, float* ot2) {
    int gx = (Hc + RPB - 1)/RPB;
    dim3 g(gx, 32);
    size_t sh = (size_t)3*(RPB+4)*Hin*sizeof(float);
    cudaFuncSetAttribute(k_conv_up_t<Hin,Hc,r,RPB,SPREV,LGIN,FUSED>,
                         cudaFuncAttributeMaxDynamicSharedMemorySize, (int)sh);
    k_conv_up_t<Hin,Hc,r,RPB,SPREV,LGIN,FUSED><<<g, 256, sh>>>(in, pt1, pt2, pab, pp2,
        ot1, ot2, b.w1, b.b1, b.w2, b.b2, b.st, b.ab, b.tk, gx*32,
        b.ip, b.lp, b.bpp, b.bnw, b.bnb, b.p1);
}

template<int Hin, int Hc, int r, int LGR, int TW, int PC, int RPB, int SPREV, int LGIN, bool FUSED, bool NOISE>
static void launch_dir(const BP& b, const float* in,
                       const float* pt1, const float* pt2,
                       const float* pab, const float* pp2, const float* pnoise,
                       float* ot1, float* ot2) {
    constexpr int NROWS = ((RPB-1)*Hc)/r + 6;
    int gx = (r/RPB) * (r/TW);
    dim3 g(gx, 32);
    size_t sh = (size_t)3*NROWS*PC*sizeof(float);
    cudaFuncSetAttribute(k_conv_dir_t<Hin,Hc,r,LGR,TW,PC,RPB,SPREV,LGIN,FUSED,NOISE>,
                         cudaFuncAttributeMaxDynamicSharedMemorySize, (int)sh);
    k_conv_dir_t<Hin,Hc,r,LGR,TW,PC,RPB,SPREV,LGIN,FUSED,NOISE><<<g, 256, sh>>>(in, pt1, pt2,
        pab, pp2, pnoise, ot1, ot2, b.w1, b.b1, b.w2, b.b2, b.st, b.ab, b.tk, gx*32,
        b.ip, b.lp, b.bpp, b.bnw, b.bnb, b.p1);
}

// ---------------- host orchestration ----------------
extern "C" void kernel_launch(void* const* d_in, const int* in_sizes, int n_in,
                              void* d_out, int out_size) {
    const float* x    = (const float*)d_in[0];
    const float* z    = (const float*)d_in[1];
    const float* linw = (const float*)d_in[2];
    const float* linb = (const float*)d_in[3];
    const float* cw   = (const float*)d_in[4];
    const float* cb   = (const float*)d_in[5];
    const float* c2w  = (const float*)d_in[6];
    const float* c2b  = (const float*)d_in[7];
    const float* qw   = (const float*)d_in[8];
    const float* qb   = (const float*)d_in[9];
    const float* kw   = (const float*)d_in[10];
    const float* kb   = (const float*)d_in[11];
    const float* vw   = (const float*)d_in[12];
    const float* vb   = (const float*)d_in[13];
    const float* inp  = (const float*)d_in[14];
    const float* lnp  = (const float*)d_in[15];
    const float* bnp  = (const float*)d_in[16];
    const float* bnw  = (const float*)d_in[17];
    const float* bnb  = (const float*)d_in[18];
    const float* p1   = (const float*)d_in[19];
    const float* p2   = (const float*)d_in[20];

    float *t1a, *t2a, *t1b, *t2b, *bufA, *bufB, *noiseB, *stats, *abt;
    int *ticket;
    cudaGetSymbolAddress((void**)&t1a,    g_t1a);
    cudaGetSymbolAddress((void**)&t2a,    g_t2a);
    cudaGetSymbolAddress((void**)&t1b,    g_t1b);
    cudaGetSymbolAddress((void**)&t2b,    g_t2b);
    cudaGetSymbolAddress((void**)&bufA,   g_bufA);
    cudaGetSymbolAddress((void**)&bufB,   g_bufB);
    cudaGetSymbolAddress((void**)&noiseB, g_noiseB);
    cudaGetSymbolAddress((void**)&stats,  g_stats);
    cudaGetSymbolAddress((void**)&abt,    g_AB12);
    cudaGetSymbolAddress((void**)&ticket, g_ticket);

    k_noise<<<1, 768>>>(z, linw, linb, cw, cb, c2w, c2b,
                        inp, lnp, bnp, bnw, bnb, p1, p2);

    auto bp = [&](int i) {
        BP b = {cw+i*225, cb+i*3, c2w+i*225, c2b+i*3,
                stats+i*192, abt+i*192, ticket+i,
                inp+3*i, lnp+3*i, bnp+3*i, bnw+3*i, bnb+3*i, p1+i};
        return b;
    };
    auto T1 = [&](int i) { return (i & 1) ? t1b : t1a; };
    auto T2 = [&](int i) { return (i & 1) ? t2b : t2a; };

    const int N = 32;
    auto att = [&](int i, int r, int S, float* outp) {
        int HW = r*r;
        k_apply_att<<<(N*HW + 255)/256, 256>>>(outp, T1(i), T2(i), abt+i*192, p2+i,
            qw+9*i, qb+3*i, kw+9*i, kb+3*i, vw+9*i, vb+3*i, N, r, S);
        dim3 ga((HW + 127)/128, N);
        k_att1<<<ga, 128>>>(HW);
        k_att2<<<ga, 128>>>(outp, HW);
    };

    // i=2: up 256->252->256, input x, RPB=8
    launch_up<256,252,256, 8, 1,0,false>(bp(2), x, nullptr, nullptr, nullptr, nullptr, T1(2), T2(2));
    // i=3: dir 256->252->128, fused from block2, RPB=8, TW=64
    launch_dir<256,252,128,7,64,136, 8, 252,8,true,false>(bp(3), nullptr, T1(2), T2(2), abt+2*192, p2+2, nullptr, T1(3), T2(3));
    // i=4: dir 128->124->64, fused from block3, RPB=8, TW=32 (column-split: grid 256->512)
    launch_dir<128,124,64,6,32,68, 8, 128,7,true,false>(bp(4), nullptr, T1(3), T2(3), abt+3*192, p2+3, nullptr, T1(4), T2(4));
    // i=5: dir 64->60->32 + noise, fused from block4, RPB=4
    launch_dir<64,60,32,5,32,68, 4, 64,6,true,true>(bp(5), nullptr, T1(4), T2(4), abt+4*192, p2+4, noiseB, T1(5), T2(5));
    att(5, 32, 32, bufA);
    // i=6: dir 32->28->16, input bufA, RPB=4
    launch_dir<32,28,16,4,16,40, 4, 1,0,false,false>(bp(6), bufA, nullptr, nullptr, nullptr, nullptr, nullptr, T1(6), T2(6));
    att(6, 16, 16, bufB);
    // i=7: up 16->12->16, input bufB, RPB=4
    launch_up<16,12,16, 4, 1,0,false>(bp(7), bufB, nullptr, nullptr, nullptr, nullptr, T1(7), T2(7));
    att(7, 16, 12, bufA);
    // i=8: up 16->12->32, input bufA, RPB=4
    launch_up<16,12,32, 4, 1,0,false>(bp(8), bufA, nullptr, nullptr, nullptr, nullptr, T1(8), T2(8));
    att(8, 32, 12, bufB);
    // i=9: up 32->28->64, input bufB, RPB=4
    launch_up<32,28,64, 4, 1,0,false>(bp(9), bufB, nullptr, nullptr, nullptr, nullptr, T1(9), T2(9));
    // i=10: up 64->60->128, fused from block9, RPB=4
    launch_up<64,60,128, 4, 28,6,true>(bp(10), nullptr, T1(9), T2(9), abt+9*192, p2+9, T1(10), T2(10));
    // i=11: up 128->124->256, fused from block10, RPB=8
    launch_up<128,124,256, 8, 60,7,true>(bp(11), nullptr, T1(10), T2(10), abt+10*192, p2+10, T1(11), T2(11));
    // final apply with tanh
    {
        int r = 256, S = 124;
        int total4 = N*3*r*(r/4);
        k_apply<<<(total4 + 255)/256, 256>>>((float*)d_out, T1(11), T2(11), abt+11*192,
                                             p2+11, N, r, S, 1);
    }
}

// round 17
// speedup vs baseline: 1.5278x; 1.5278x over previous
#include <cuda_runtime.h>
#include <math.h>

#define EPSV 1e-5f
#define L2E 1.4426950408889634f

// ---------------- scratch ----------------
__device__ float g_t1a[32*3*252*252];
__device__ float g_t2a[32*3*252*252];
__device__ float g_t1b[32*3*252*252];
__device__ float g_t2b[32*3*252*252];
__device__ float g_bufA[32*3*1024];
__device__ float g_bufB[32*3*1024];
__device__ float g_stats[12*96*2];
__device__ float g_AB12[12*96*2];
__device__ int   g_ticket[12];
__device__ float g_noiseB[3*64*64];
__device__ float4 g_q4[32*1024];
__device__ float4 g_k4[32*1024];
__device__ float4 g_v4[32*1024];
__device__ float4 g_w4[32*1024];

// ---------------- tiny helpers ----------------
__device__ __forceinline__ float ex2(float x) {
    float r; asm("ex2.approx.ftz.f32 %0,%1;" : "=f"(r) : "f"(x)); return r;
}
__device__ __forceinline__ float frcp(float x) {
    float r; asm("rcp.approx.ftz.f32 %0,%1;" : "=f"(r) : "f"(x)); return r;
}
__device__ __forceinline__ float ftanh(float x) {
    float e = ex2(x * 2.885390081777927f);
    return fmaf(-2.f, frcp(e + 1.f), 1.f);
}

// ---------------- stats reduction ----------------
__device__ __forceinline__ void stats_reduce(float s0, float s1, float s2,
                                             float q0, float q1, float q2,
                                             float* stats, int n) {
    #pragma unroll
    for (int off = 16; off; off >>= 1) {
        s0 += __shfl_down_sync(0xffffffffu, s0, off);
        s1 += __shfl_down_sync(0xffffffffu, s1, off);
        s2 += __shfl_down_sync(0xffffffffu, s2, off);
        q0 += __shfl_down_sync(0xffffffffu, q0, off);
        q1 += __shfl_down_sync(0xffffffffu, q1, off);
        q2 += __shfl_down_sync(0xffffffffu, q2, off);
    }
    __shared__ float rb[8][6];
    int warp = threadIdx.x >> 5, lane = threadIdx.x & 31;
    if (lane == 0) {
        rb[warp][0]=s0; rb[warp][1]=s1; rb[warp][2]=s2;
        rb[warp][3]=q0; rb[warp][4]=q1; rb[warp][5]=q2;
    }
    __syncthreads();
    if (threadIdx.x == 0) {
        float a[6] = {0,0,0,0,0,0};
        int nw = blockDim.x >> 5;
        for (int wi = 0; wi < nw; wi++)
            for (int t = 0; t < 6; t++) a[t] += rb[wi][t];
        #pragma unroll
        for (int c = 0; c < 3; c++) {
            atomicAdd(&stats[(n*3+c)*2+0], a[c]);
            atomicAdd(&stats[(n*3+c)*2+1], a[3+c]);
        }
    }
}

// ---------------- last-block finalize ----------------
__device__ __forceinline__ void finalize_if_last(const float* __restrict__ st, float* __restrict__ ab,
        int* ticket, int nblocks,
        const float* ip, const float* lp, const float* bp,
        const float* bnw, const float* bnb, const float* p1p, int N, float cnt) {
    __shared__ int slast;
    if (threadIdx.x == 0) {
        __threadfence();
        int t = atomicAdd(ticket, 1);
        slast = (t == nblocks - 1) ? 1 : 0;
    }
    __syncthreads();
    if (!slast) return;
    __shared__ float s_s[96], s_q[96], s_bs[3], s_bq[3];
    int tid = threadIdx.x;
    if (tid < N*3) {
        s_s[tid] = __ldcg(st + tid*2);
        s_q[tid] = __ldcg(st + tid*2 + 1);
    }
    __syncthreads();
    if (tid < 3) {
        float a = 0.f, b = 0.f;
        for (int n = 0; n < N; n++) { a += s_s[n*3+tid]; b += s_q[n*3+tid]; }
        s_bs[tid] = a; s_bq[tid] = b;
    }
    __syncthreads();
    if (tid < N*3) {
        int c = tid % 3;
        float mI = s_s[tid]/cnt, vI = s_q[tid]/cnt - mI*mI;
        float rI = rsqrtf(vI + EPSV);
        float cb = cnt * (float)N;
        float mB = s_bs[c]/cb, vB = s_bq[c]/cb - mB*mB;
        float rB = rsqrtf(vB + EPSV);
        float alpha = __ldg(ip)+__ldg(ip+1)+__ldg(ip+2)+__ldg(lp)+__ldg(lp+1)+__ldg(lp+2);
        float beta  = __ldg(bp)+__ldg(bp+1)+__ldg(bp+2);
        float bw = __ldg(bnw+c), bb2 = __ldg(bnb+c), P1 = __ldg(p1p);
        ab[tid*2]   = P1*(1.f + alpha*rI + beta*rB*bw);
        ab[tid*2+1] = P1*(beta*(bb2 - mB*rB*bw) - alpha*mI*rI);
    }
}

// ---------------- weight pack ----------------
__device__ __forceinline__ void load_weights(const float* w1, const float* w2, float* sw8) {
    for (int j = threadIdx.x; j < 600; j += blockDim.x) {
        int slot = j & 7, pos = j >> 3;
        float v = 0.f;
        if (slot < 3)      v = __ldg(w1 + slot*75 + pos);
        else if (slot < 6) v = __ldg(w2 + (slot-3)*75 + pos);
        sw8[j] = v;
    }
}

// ---------------- upsample-path conv ----------------
template<int Hin, int Hc, int r, int RPB, int SPREV, int LGIN, bool FUSED>
__global__ void __launch_bounds__(256, 4)
k_conv_up_t(const float* __restrict__ in,
            const float* __restrict__ pt1, const float* __restrict__ pt2,
            const float* __restrict__ pab, const float* pp2,
            float* __restrict__ ot1, float* __restrict__ ot2,
            const float* __restrict__ w1, const float* __restrict__ b1,
            const float* __restrict__ w2, const float* __restrict__ b2,
            float* stats, float* ab, int* ticket, int nblocks,
            const float* ip, const float* lp, const float* bp,
            const float* bnw, const float* bnb, const float* p1p) {
    constexpr int SR = RPB + 4;
    __shared__ float sw8[600];
    extern __shared__ float dsin[];           // [3][SR][Hin]
    load_weights(w1, w2, sw8);
    int n = blockIdx.y;
    int h0 = blockIdx.x * RPB;
    if (FUSED) {
        float P2 = __ldg(pp2);
        for (int j = threadIdx.x; j < 3*SR*Hin; j += 256) {
            int ci = j / (SR*Hin), rem = j - ci*(SR*Hin);
            int row = rem / Hin, col = rem - row*Hin;
            int gr = h0 + row; gr = (gr < Hin) ? gr : Hin-1;
            int nc3 = n*3 + ci;
            float A = __ldg(pab + nc3*2), B = __ldg(pab + nc3*2 + 1);
            int sh2 = (gr*SPREV) >> LGIN, sw2 = (col*SPREV) >> LGIN;
            long sidx = ((long)nc3*SPREV + sh2)*SPREV + sw2;
            dsin[(ci*SR + row)*Hin + col] =
                fmaf(__ldg(pt1 + sidx), A, B) + P2*__ldg(pt2 + sidx);
        }
    } else {
        constexpr int W4 = Hin / 4;
        const float4* src = (const float4*)(in + (long)n*3*Hin*Hin);
        for (int j = threadIdx.x; j < 3*SR*W4; j += 256) {
            int ci = j / (SR*W4), rem = j - ci*(SR*W4);
            int row = rem / W4, col = rem - row*W4;
            int gr = h0 + row; gr = (gr < Hin) ? gr : Hin-1;
            ((float4*)dsin)[(ci*SR + row)*W4 + col] = __ldg(src + (ci*Hin + gr)*W4 + col);
        }
    }
    __syncthreads();
    int warp = threadIdx.x >> 5, lane = threadIdx.x & 31;
    int rloc = warp % RPB;
    int sgrp = warp / RPB;
    constexpr int NSG = 8 / RPB;
    int sh = h0 + rloc;
    constexpr int STRIPS = Hc / 4;
    float a0=0,a1=0,a2=0,q0=0,q1=0,q2=0;
    if (sh < Hc) {
        float wrow = (float)((((sh+1)*r + Hc - 1)/Hc) - ((sh*r + Hc - 1)/Hc));
        #pragma unroll 1
        for (int strip = lane + 32*sgrp; strip < STRIPS; strip += 32*NSG) {
            int sw0 = strip * 4;
            float acc[6][4];
            #pragma unroll
            for (int f = 0; f < 6; f++) {
                float bb = (f < 3) ? __ldg(b1+f) : __ldg(b2+f-3);
                #pragma unroll
                for (int p = 0; p < 4; p++) acc[f][p] = bb;
            }
            #pragma unroll
            for (int ci = 0; ci < 3; ci++) {
                #pragma unroll
                for (int kh = 0; kh < 5; kh++) {
                    const float* srow = dsin + ((ci*SR + rloc + kh)*Hin + sw0);
                    float4 xa = *(const float4*)(srow);
                    float4 xb = *(const float4*)(srow + 4);
                    float xv[8] = {xa.x, xa.y, xa.z, xa.w, xb.x, xb.y, xb.z, xb.w};
                    const float* wr = sw8 + (ci*25 + kh*5)*8;
                    #pragma unroll
                    for (int kw = 0; kw < 5; kw++) {
                        float4 wa = *(const float4*)(wr + kw*8);
                        float2 wb = *(const float2*)(wr + kw*8 + 4);
                        #pragma unroll
                        for (int p = 0; p < 4; p++) {
                            float xx = xv[p+kw];
                            acc[0][p] = fmaf(wa.x, xx, acc[0][p]);
                            acc[1][p] = fmaf(wa.y, xx, acc[1][p]);
                            acc[2][p] = fmaf(wa.z, xx, acc[2][p]);
                            acc[3][p] = fmaf(wa.w, xx, acc[3][p]);
                            acc[4][p] = fmaf(wb.x, xx, acc[4][p]);
                            acc[5][p] = fmaf(wb.y, xx, acc[5][p]);
                        }
                    }
                }
            }
            constexpr int chs = Hc*Hc;
            long base = ((long)(n*3)*Hc + sh)*Hc + sw0;
            #pragma unroll
            for (int p = 0; p < 4; p++) {
                int swp = sw0 + p;
                float wcol = (float)((((swp+1)*r + Hc - 1)/Hc) - ((swp*r + Hc - 1)/Hc));
                float wgt = wrow * wcol;
                float y0 = acc[0][p], y1 = acc[1][p], y2 = acc[2][p];
                ot1[base + p]         = y0;
                ot1[base + chs + p]   = y1;
                ot1[base + 2*chs + p] = y2;
                ot2[base + p]         = acc[3][p];
                ot2[base + chs + p]   = acc[4][p];
                ot2[base + 2*chs + p] = acc[5][p];
                a0 += wgt*y0; q0 += wgt*y0*y0;
                a1 += wgt*y1; q1 += wgt*y1*y1;
                a2 += wgt*y2; q2 += wgt*y2*y2;
            }
        }
    }
    stats_reduce(a0, a1, a2, q0, q1, q2, stats, n);
    finalize_if_last(stats, ab, ticket, nblocks, ip, lp, bp, bnw, bnb, p1p, 32, (float)(r*r));
}

// ---------------- downsample-path conv ----------------
template<int Hin, int Hc, int r, int LGR, int TW, int PC, int RPB, int SPREV, int LGIN, bool FUSED, bool NOISE>
__global__ void __launch_bounds__(256, 4)
k_conv_dir_t(const float* __restrict__ in,
             const float* __restrict__ pt1, const float* __restrict__ pt2,
             const float* __restrict__ pab, const float* pp2,
             const float* __restrict__ pnoise,
             float* __restrict__ ot1, float* __restrict__ ot2,
             const float* __restrict__ w1, const float* __restrict__ b1,
             const float* __restrict__ w2, const float* __restrict__ b2,
             float* stats, float* ab, int* ticket, int nblocks,
             const float* ip, const float* lp, const float* bp,
             const float* bnw, const float* bnb, const float* p1p) {
    constexpr int NROWS = ((RPB-1)*Hc)/r + 6;
    constexpr int XT = r / TW;
    __shared__ float sw8[600];
    extern __shared__ float dsin[];           // [3][NROWS][PC]
    load_weights(w1, w2, sw8);
    int n = blockIdx.y;
    int tile = blockIdx.x;
    int tyt = tile / XT, txt = tile - tyt*XT;
    int h0 = tyt * RPB;
    int w0 = txt * TW;
    int s0 = (h0*Hc) >> LGR;
    int sw0a = ((w0*Hc) >> LGR) & ~3;
    if (FUSED) {
        float P2 = __ldg(pp2);
        for (int j = threadIdx.x; j < 3*NROWS*PC; j += 256) {
            int ci = j / (NROWS*PC), rem = j - ci*(NROWS*PC);
            int row = rem / PC, col = rem - row*PC;
            int gr = s0 + row; gr = (gr < Hin) ? gr : Hin-1;
            int gc = sw0a + col; gc = (gc < Hin) ? gc : Hin-1;
            int nc3 = n*3 + ci;
            float A = __ldg(pab + nc3*2), B = __ldg(pab + nc3*2 + 1);
            int sh2 = (gr*SPREV) >> LGIN, sw2 = (gc*SPREV) >> LGIN;
            long sidx = ((long)nc3*SPREV + sh2)*SPREV + sw2;
            float v = fmaf(__ldg(pt1 + sidx), A, B) + P2*__ldg(pt2 + sidx);
            if (NOISE) v += __ldg(pnoise + (ci*Hin + gr)*Hin + gc);
            dsin[(ci*NROWS + row)*PC + col] = v;
        }
    } else {
        constexpr int W4 = Hin / 4;
        constexpr int PC4 = PC / 4;
        const float4* src = (const float4*)(in + (long)n*3*Hin*Hin);
        for (int j = threadIdx.x; j < 3*NROWS*PC4; j += 256) {
            int ci = j / (NROWS*PC4), rem = j - ci*(NROWS*PC4);
            int row = rem / PC4, col4 = rem - row*PC4;
            int gr = s0 + row; gr = (gr < Hin) ? gr : Hin-1;
            int gc4 = (sw0a >> 2) + col4; gc4 = (gc4 < W4) ? gc4 : W4-1;
            *(float4*)(dsin + (ci*NROWS + row)*PC + col4*4) = __ldg(src + (ci*Hin + gr)*W4 + gc4);
        }
    }
    __syncthreads();
    int warp = threadIdx.x >> 5, lane = threadIdx.x & 31;
    int rloc = warp % RPB;
    int wgrp = warp / RPB;
    constexpr int NSG = 8 / RPB;
    int h = h0 + rloc;
    int shl = ((h*Hc) >> LGR) - s0;
    float a0=0,a1=0,a2=0,q0=0,q1=0,q2=0;
    #pragma unroll 1
    for (int wi = lane + 32*wgrp; wi < TW; wi += 32*NSG) {
        int w = w0 + wi;
        int swl = ((w*Hc) >> LGR) - sw0a;
        float acc[6];
        #pragma unroll
        for (int f = 0; f < 6; f++)
            acc[f] = (f < 3) ? __ldg(b1+f) : __ldg(b2+f-3);
        #pragma unroll
        for (int ci = 0; ci < 3; ci++) {
            #pragma unroll
            for (int kh = 0; kh < 5; kh++) {
                const float* srow = dsin + ((ci*NROWS + shl + kh)*PC + swl);
                float xv[5];
                #pragma unroll
                for (int j = 0; j < 5; j++) xv[j] = srow[j];
                const float* wr = sw8 + (ci*25 + kh*5)*8;
                #pragma unroll
                for (int kw = 0; kw < 5; kw++) {
                    float4 wa = *(const float4*)(wr + kw*8);
                    float2 wb = *(const float2*)(wr + kw*8 + 4);
                    float xx = xv[kw];
                    acc[0] = fmaf(wa.x, xx, acc[0]);
                    acc[1] = fmaf(wa.y, xx, acc[1]);
                    acc[2] = fmaf(wa.z, xx, acc[2]);
                    acc[3] = fmaf(wa.w, xx, acc[3]);
                    acc[4] = fmaf(wb.x, xx, acc[4]);
                    acc[5] = fmaf(wb.y, xx, acc[5]);
                }
            }
        }
        constexpr int rs = r*r;
        long base = (long)(n*3)*rs + h*r + w;
        ot1[base]        = acc[0];
        ot1[base + rs]   = acc[1];
        ot1[base + 2*rs] = acc[2];
        ot2[base]        = acc[3];
        ot2[base + rs]   = acc[4];
        ot2[base + 2*rs] = acc[5];
        a0 += acc[0]; q0 += acc[0]*acc[0];
        a1 += acc[1]; q1 += acc[1]*acc[1];
        a2 += acc[2]; q2 += acc[2]*acc[2];
    }
    stats_reduce(a0, a1, a2, q0, q1, q2, stats, n);
    finalize_if_last(stats, ab, ticket, nblocks, ip, lp, bp, bnw, bnb, p1p, 32, (float)(r*r));
}

// ---------------- apply (final block only) ----------------
__global__ void k_apply(float* __restrict__ out,
                        const float* __restrict__ t1, const float* __restrict__ t2,
                        const float* __restrict__ ab,
                        const float* p2p, int N, int r, int S, int dotanh) {
    int rq = r >> 2;
    int idx = blockIdx.x*blockDim.x + threadIdx.x;
    if (idx >= N*3*r*rq) return;
    int w0 = (idx % rq)*4; int t = idx / rq; int h = t % r; int nc = t / r;
    float A = __ldg(ab + nc*2), B = __ldg(ab + nc*2 + 1), P2 = __ldg(p2p);
    float v[4];
    if (S == r) {
        long sb = ((long)nc*S + h)*S + w0;
        float4 t1v = *(const float4*)(t1 + sb);
        float4 t2v = *(const float4*)(t2 + sb);
        v[0] = fmaf(t1v.x, A, B) + P2*t2v.x;
        v[1] = fmaf(t1v.y, A, B) + P2*t2v.y;
        v[2] = fmaf(t1v.z, A, B) + P2*t2v.z;
        v[3] = fmaf(t1v.w, A, B) + P2*t2v.w;
    } else {
        int sh = (h*S)/r;
        long rb = ((long)nc*S + sh)*S;
        #pragma unroll
        for (int p = 0; p < 4; p++) {
            int sw = ((w0+p)*S)/r;
            v[p] = fmaf(t1[rb+sw], A, B) + P2*t2[rb+sw];
        }
    }
    if (dotanh) {
        #pragma unroll
        for (int p = 0; p < 4; p++) v[p] = ftanh(v[p]);
    }
    *(float4*)(out + (long)idx*4) = make_float4(v[0], v[1], v[2], v[3]);
}

// ---------------- apply + qkv fused (attention blocks) ----------------
__global__ void k_apply_att(float* __restrict__ out,
                            const float* __restrict__ t1, const float* __restrict__ t2,
                            const float* __restrict__ ab, const float* p2p,
                            const float* qw, const float* qb,
                            const float* kw_, const float* kb,
                            const float* vw, const float* vb,
                            int N, int r, int S) {
    int HW = r*r;
    int idx = blockIdx.x*blockDim.x + threadIdx.x;
    if (idx >= N*HW) return;
    int b = idx / HW, pix = idx - b*HW;
    int h = pix / r, w = pix - h*r;
    int sh = (h*S)/r, sw = (w*S)/r;
    float P2 = __ldg(p2p);
    long sbase = ((long)(b*3)*S + sh)*S + sw;
    int ss2 = S*S;
    float val[3];
    #pragma unroll
    for (int c = 0; c < 3; c++) {
        float A = __ldg(ab + (b*3+c)*2), B = __ldg(ab + (b*3+c)*2 + 1);
        val[c] = fmaf(t1[sbase + c*ss2], A, B) + P2*t2[sbase + c*ss2];
    }
    long ob = (long)b*3*HW + pix;
    out[ob] = val[0]; out[ob+HW] = val[1]; out[ob+2*HW] = val[2];
    float qv[3], kv[3], vv[3];
    #pragma unroll
    for (int o = 0; o < 3; o++) {
        qv[o] = fmaf(__ldg(qw+o*3), val[0], fmaf(__ldg(qw+o*3+1), val[1],
                fmaf(__ldg(qw+o*3+2), val[2], __ldg(qb+o))));
        kv[o] = fmaf(__ldg(kw_+o*3), val[0], fmaf(__ldg(kw_+o*3+1), val[1],
                fmaf(__ldg(kw_+o*3+2), val[2], __ldg(kb+o))));
        vv[o] = fmaf(__ldg(vw+o*3), val[0], fmaf(__ldg(vw+o*3+1), val[1],
                fmaf(__ldg(vw+o*3+2), val[2], __ldg(vb+o))));
    }
    g_q4[b*HW+pix] = make_float4(qv[0], qv[1], qv[2], 0.f);
    g_k4[b*HW+pix] = make_float4(kv[0], kv[1], kv[2], 0.f);
    g_v4[b*HW+pix] = make_float4(vv[0], vv[1], vv[2], 0.f);
}

// ---------------- attention pass 1 (R10-proven, full grid) ----------------
__global__ void k_att1(int HW) {
    __shared__ float4 sq[1024];
    int b = blockIdx.y;
    for (int j = threadIdx.x; j < HW; j += blockDim.x) sq[j] = g_q4[b*HW+j];
    __syncthreads();
    int m = blockIdx.x*blockDim.x + threadIdx.x;
    if (m >= HW) return;
    float4 kk = g_k4[b*HW+m];
    float k0 = kk.x*L2E, k1 = kk.y*L2E, k2 = kk.z*L2E;
    float mx = -1e30f;
    for (int nn = 0; nn < HW; nn++) {
        float4 q = sq[nn];
        float s = fmaf(k0, q.x, fmaf(k1, q.y, k2*q.z));
        mx = fmaxf(mx, s);
    }
    float Z = 0.f;
    for (int nn = 0; nn < HW; nn++) {
        float4 q = sq[nn];
        float s = fmaf(k0, q.x, fmaf(k1, q.y, k2*q.z));
        Z += ex2(s - mx);
    }
    float iz = frcp(Z);
    g_k4[b*HW+m] = make_float4(k0, k1, k2, mx);
    float4 v = g_v4[b*HW+m];
    g_w4[b*HW+m] = make_float4(v.x*iz, v.y*iz, v.z*iz, 0.f);
}

// ---------------- attention pass 2 (R10-proven, full grid) ----------------
__global__ void k_att2(float* __restrict__ out, int HW) {
    __shared__ float4 sk[1024];
    __shared__ float4 sw[1024];
    int b = blockIdx.y;
    for (int j = threadIdx.x; j < HW; j += blockDim.x) {
        sk[j] = g_k4[b*HW+j];
        sw[j] = g_w4[b*HW+j];
    }
    __syncthreads();
    int nn = blockIdx.x*blockDim.x + threadIdx.x;
    if (nn >= HW) return;
    float4 q = g_q4[b*HW+nn];
    float a0 = 0.f, a1 = 0.f, a2 = 0.f;
    for (int m = 0; m < HW; m++) {
        float4 kk = sk[m];
        float s = fmaf(kk.x, q.x, fmaf(kk.y, q.y, kk.z*q.z));
        float e = ex2(s - kk.w);
        float4 w = sw[m];
        a0 = fmaf(w.x, e, a0);
        a1 = fmaf(w.y, e, a1);
        a2 = fmaf(w.z, e, a2);
    }
    long ob = (long)b*3*HW + nn;
    out[ob]        += a0;
    out[ob+HW]     += a1;
    out[ob+2*HW]   += a2;
}

// ---------------- fused noise path (separate launch, R10-proven) ----------------
__device__ void nblock(const float* xin, float* y1, float* y2, float* xout,
                       int Hin, int Hc, int r,
                       const float* w1, const float* b1, const float* w2, const float* b2,
                       const float* ip, const float* lp, const float* bp,
                       const float* bw_, const float* bb_, float P1, float P2) {
    __shared__ float swn[450];
    __shared__ float sacc[6];
    __shared__ float sAB2[6];
    int tid = threadIdx.x, nt = blockDim.x;
    for (int j = tid; j < 450; j += nt) {
        int slot = j % 6, pos = j / 6;
        swn[j] = (slot < 3) ? __ldg(w1 + slot*75 + pos) : __ldg(w2 + (slot-3)*75 + pos);
    }
    if (tid < 6) sacc[tid] = 0.f;
    __syncthreads();
    float ls[6] = {0,0,0,0,0,0};
    int hc2 = Hc*Hc;
    for (int pix = tid; pix < hc2; pix += nt) {
        int sh = pix / Hc, sw = pix - sh*Hc;
        float a[6];
        #pragma unroll
        for (int f = 0; f < 6; f++) a[f] = (f < 3) ? __ldg(b1+f) : __ldg(b2+f-3);
        for (int ci = 0; ci < 3; ci++)
            for (int kh = 0; kh < 5; kh++) {
                const float* row = xin + (ci*Hin + sh + kh)*Hin + sw;
                const float* wr = swn + (ci*25 + kh*5)*6;
                #pragma unroll
                for (int kw = 0; kw < 5; kw++) {
                    float xx = row[kw];
                    #pragma unroll
                    for (int f = 0; f < 6; f++) a[f] = fmaf(wr[kw*6+f], xx, a[f]);
                }
            }
        float wrow = (float)((((sh+1)*r + Hc - 1)/Hc) - ((sh*r + Hc - 1)/Hc));
        float wcol = (float)((((sw+1)*r + Hc - 1)/Hc) - ((sw*r + Hc - 1)/Hc));
        float wgt = wrow * wcol;
        #pragma unroll
        for (int c = 0; c < 3; c++) {
            y1[c*hc2 + pix] = a[c];
            y2[c*hc2 + pix] = a[3+c];
            ls[c]   += wgt * a[c];
            ls[3+c] += wgt * a[c]*a[c];
        }
    }
    #pragma unroll
    for (int j = 0; j < 6; j++) atomicAdd(&sacc[j], ls[j]);
    __syncthreads();
    if (tid < 3) {
        float cnt = (float)(r*r);
        float mI = sacc[tid]/cnt, vI = sacc[3+tid]/cnt - mI*mI;
        float rI = rsqrtf(vI + EPSV);
        float alpha = __ldg(ip)+__ldg(ip+1)+__ldg(ip+2)+__ldg(lp)+__ldg(lp+1)+__ldg(lp+2);
        float beta  = __ldg(bp)+__ldg(bp+1)+__ldg(bp+2);
        float bw = __ldg(bw_+tid), bb2 = __ldg(bb_+tid);
        sAB2[tid]   = P1*(1.f + alpha*rI + beta*rI*bw);
        sAB2[3+tid] = P1*(beta*(bb2 - mI*rI*bw) - alpha*mI*rI);
    }
    __syncthreads();
    int rr = r*r;
    for (int e = tid; e < 3*rr; e += nt) {
        int c = e / rr, pix = e - c*rr;
        int h = pix / r, w = pix - h*r;
        int sh = (h*Hc)/r, sw = (w*Hc)/r;
        int si = c*hc2 + sh*Hc + sw;
        xout[e] = fmaf(y1[si], sAB2[c], sAB2[3+c]) + P2*y2[si];
    }
    __syncthreads();
}

__global__ void k_noise(const float* __restrict__ z,
                        const float* __restrict__ Wl, const float* __restrict__ bl,
                        const float* cw, const float* cb, const float* c2w, const float* c2b,
                        const float* inp, const float* lnp, const float* bnp,
                        const float* bnw, const float* bnb,
                        const float* p1, const float* p2) {
    __shared__ float sl[768];
    __shared__ float y1a[3*144], y2a[3*144];
    __shared__ float x1[3*1024];
    __shared__ float y1b[3*784], y2b[3*784];
    int tid = threadIdx.x;
    for (int j = tid; j < 12*96*2; j += blockDim.x) g_stats[j] = 0.f;
    if (tid < 12) g_ticket[tid] = 0;
    int warp = tid >> 5, lane = tid & 31;
    for (int o = warp; o < 768; o += (int)(blockDim.x >> 5)) {
        const float* w = Wl + o*512;
        float a = 0.f;
        for (int j = lane; j < 512; j += 32) a = fmaf(__ldg(z+j), __ldg(w+j), a);
        #pragma unroll
        for (int off = 16; off; off >>= 1) a += __shfl_down_sync(0xffffffffu, a, off);
        if (lane == 0) sl[o] = a + __ldg(bl + o);
    }
    __syncthreads();
    nblock(sl, y1a, y2a, x1, 16, 12, 32, cw, cb, c2w, c2b,
           inp, lnp, bnp, bnw, bnb, __ldg(p1), __ldg(p2));
    nblock(x1, y1b, y2b, g_noiseB, 32, 28, 64, cw+225, cb+3, c2w+225, c2b+3,
           inp+3, lnp+3, bnp+3, bnw+3, bnb+3, __ldg(p1+1), __ldg(p2+1));
}

// ---------------- host launchers ----------------
struct BP {
    const float *w1, *b1, *w2, *b2;
    float *st, *ab; int *tk;
    const float *ip, *lp, *bpp, *bnw, *bnb, *p1;
};

template<int Hin, int Hc, int r, int RPB, int SPREV, int LGIN, bool FUSED>
static void launch_up(const BP& b, const float* in,
                      const float* pt1, const float* pt2,
                      const float* pab, const float* pp2,
                      float* ot1, float* ot2) {
    int gx = (Hc + RPB - 1)/RPB;
    dim3 g(gx, 32);
    size_t sh = (size_t)3*(RPB+4)*Hin*sizeof(float);
    cudaFuncSetAttribute(k_conv_up_t<Hin,Hc,r,RPB,SPREV,LGIN,FUSED>,
                         cudaFuncAttributeMaxDynamicSharedMemorySize, (int)sh);
    k_conv_up_t<Hin,Hc,r,RPB,SPREV,LGIN,FUSED><<<g, 256, sh>>>(in, pt1, pt2, pab, pp2,
        ot1, ot2, b.w1, b.b1, b.w2, b.b2, b.st, b.ab, b.tk, gx*32,
        b.ip, b.lp, b.bpp, b.bnw, b.bnb, b.p1);
}

template<int Hin, int Hc, int r, int LGR, int TW, int PC, int RPB, int SPREV, int LGIN, bool FUSED, bool NOISE>
static void launch_dir(const BP& b, const float* in,
                       const float* pt1, const float* pt2,
                       const float* pab, const float* pp2, const float* pnoise,
                       float* ot1, float* ot2) {
    constexpr int NROWS = ((RPB-1)*Hc)/r + 6;
    int gx = (r/RPB) * (r/TW);
    dim3 g(gx, 32);
    size_t sh = (size_t)3*NROWS*PC*sizeof(float);
    cudaFuncSetAttribute(k_conv_dir_t<Hin,Hc,r,LGR,TW,PC,RPB,SPREV,LGIN,FUSED,NOISE>,
                         cudaFuncAttributeMaxDynamicSharedMemorySize, (int)sh);
    k_conv_dir_t<Hin,Hc,r,LGR,TW,PC,RPB,SPREV,LGIN,FUSED,NOISE><<<g, 256, sh>>>(in, pt1, pt2,
        pab, pp2, pnoise, ot1, ot2, b.w1, b.b1, b.w2, b.b2, b.st, b.ab, b.tk, gx*32,
        b.ip, b.lp, b.bpp, b.bnw, b.bnb, b.p1);
}

// ---------------- host orchestration ----------------
extern "C" void kernel_launch(void* const* d_in, const int* in_sizes, int n_in,
                              void* d_out, int out_size) {
    const float* x    = (const float*)d_in[0];
    const float* z    = (const float*)d_in[1];
    const float* linw = (const float*)d_in[2];
    const float* linb = (const float*)d_in[3];
    const float* cw   = (const float*)d_in[4];
    const float* cb   = (const float*)d_in[5];
    const float* c2w  = (const float*)d_in[6];
    const float* c2b  = (const float*)d_in[7];
    const float* qw   = (const float*)d_in[8];
    const float* qb   = (const float*)d_in[9];
    const float* kw   = (const float*)d_in[10];
    const float* kb   = (const float*)d_in[11];
    const float* vw   = (const float*)d_in[12];
    const float* vb   = (const float*)d_in[13];
    const float* inp  = (const float*)d_in[14];
    const float* lnp  = (const float*)d_in[15];
    const float* bnp  = (const float*)d_in[16];
    const float* bnw  = (const float*)d_in[17];
    const float* bnb  = (const float*)d_in[18];
    const float* p1   = (const float*)d_in[19];
    const float* p2   = (const float*)d_in[20];

    float *t1a, *t2a, *t1b, *t2b, *bufA, *bufB, *noiseB, *stats, *abt;
    int *ticket;
    cudaGetSymbolAddress((void**)&t1a,    g_t1a);
    cudaGetSymbolAddress((void**)&t2a,    g_t2a);
    cudaGetSymbolAddress((void**)&t1b,    g_t1b);
    cudaGetSymbolAddress((void**)&t2b,    g_t2b);
    cudaGetSymbolAddress((void**)&bufA,   g_bufA);
    cudaGetSymbolAddress((void**)&bufB,   g_bufB);
    cudaGetSymbolAddress((void**)&noiseB, g_noiseB);
    cudaGetSymbolAddress((void**)&stats,  g_stats);
    cudaGetSymbolAddress((void**)&abt,    g_AB12);
    cudaGetSymbolAddress((void**)&ticket, g_ticket);

    k_noise<<<1, 768>>>(z, linw, linb, cw, cb, c2w, c2b,
                        inp, lnp, bnp, bnw, bnb, p1, p2);

    auto bp = [&](int i) {
        BP b = {cw+i*225, cb+i*3, c2w+i*225, c2b+i*3,
                stats+i*192, abt+i*192, ticket+i,
                inp+3*i, lnp+3*i, bnp+3*i, bnw+3*i, bnb+3*i, p1+i};
        return b;
    };
    auto T1 = [&](int i) { return (i & 1) ? t1b : t1a; };
    auto T2 = [&](int i) { return (i & 1) ? t2b : t2a; };

    const int N = 32;
    auto att = [&](int i, int r, int S, float* outp) {
        int HW = r*r;
        k_apply_att<<<(N*HW + 255)/256, 256>>>(outp, T1(i), T2(i), abt+i*192, p2+i,
            qw+9*i, qb+3*i, kw+9*i, kb+3*i, vw+9*i, vb+3*i, N, r, S);
        dim3 ga((HW + 127)/128, N);
        k_att1<<<ga, 128>>>(HW);
        k_att2<<<ga, 128>>>(outp, HW);
    };

    // i=2: up 256->252->256, input x, RPB=8
    launch_up<256,252,256, 8, 1,0,false>(bp(2), x, nullptr, nullptr, nullptr, nullptr, T1(2), T2(2));
    // i=3: dir 256->252->128, fused from block2, RPB=8, TW=64
    launch_dir<256,252,128,7,64,136, 8, 252,8,true,false>(bp(3), nullptr, T1(2), T2(2), abt+2*192, p2+2, nullptr, T1(3), T2(3));
    // i=4: dir 128->124->64, fused from block3, RPB=8, TW=64 (R12/R14-measured best: 20.8us)
    launch_dir<128,124,64,6,64,136, 8, 128,7,true,false>(bp(4), nullptr, T1(3), T2(3), abt+3*192, p2+3, nullptr, T1(4), T2(4));
    // i=5: dir 64->60->32 + noise, fused from block4, RPB=4
    launch_dir<64,60,32,5,32,68, 4, 64,6,true,true>(bp(5), nullptr, T1(4), T2(4), abt+4*192, p2+4, noiseB, T1(5), T2(5));
    att(5, 32, 32, bufA);
    // i=6: dir 32->28->16, input bufA, RPB=4
    launch_dir<32,28,16,4,16,40, 4, 1,0,false,false>(bp(6), bufA, nullptr, nullptr, nullptr, nullptr, nullptr, T1(6), T2(6));
    att(6, 16, 16, bufB);
    // i=7: up 16->12->16, input bufB, RPB=4
    launch_up<16,12,16, 4, 1,0,false>(bp(7), bufB, nullptr, nullptr, nullptr, nullptr, T1(7), T2(7));
    att(7, 16, 12, bufA);
    // i=8: up 16->12->32, input bufA, RPB=4
    launch_up<16,12,32, 4, 1,0,false>(bp(8), bufA, nullptr, nullptr, nullptr, nullptr, T1(8), T2(8));
    att(8, 32, 12, bufB);
    // i=9: up 32->28->64, input bufB, RPB=4
    launch_up<32,28,64, 4, 1,0,false>(bp(9), bufB, nullptr, nullptr, nullptr, nullptr, T1(9), T2(9));
    // i=10: up 64->60->128, fused from block9, RPB=4
    launch_up<64,60,128, 4, 28,6,true>(bp(10), nullptr, T1(9), T2(9), abt+9*192, p2+9, T1(10), T2(10));
    // i=11: up 128->124->256, fused from block10, RPB=8
    launch_up<128,124,256, 8, 60,7,true>(bp(11), nullptr, T1(10), T2(10), abt+10*192, p2+10, T1(11), T2(11));
    // final apply with tanh
    {
        int r = 256, S = 124;
        int total4 = N*3*r*(r/4);
        k_apply<<<(total4 + 255)/256, 256>>>((float*)d_out, T1(11), T2(11), abt+11*192,
                                             p2+11, N, r, S, 1);
    }
}